// round 8
// baseline (speedup 1.0000x reference)
#include <cuda_runtime.h>
#include <cuda_fp16.h>
#include <cstdint>

#define NODES_TOTAL 100000
#define NNODES      20000
#define TN          50
#define INF         256
#define HIDF        256
#define OUTF        256
#define CATF        512

// Scratch (static __device__ arrays: allocation-free per harness rules)
__device__ __align__(16) __half g_qh[(size_t)NODES_TOTAL * HIDF];  // 51.2 MB (L2-resident)
__device__ __align__(16) __half g_cat[(size_t)NNODES * CATF];      // 20.5 MB

// ---------------------------------------------------------------------------
// helpers
// ---------------------------------------------------------------------------
__device__ __forceinline__ void mma_f16_f32acc(float c[4], const uint32_t a[4],
                                               uint32_t b0, uint32_t b1) {
    asm volatile("mma.sync.aligned.m16n8k16.row.col.f32.f16.f16.f32 "
                 "{%0,%1,%2,%3}, {%4,%5,%6,%7}, {%8,%9}, {%0,%1,%2,%3};"
                 : "+f"(c[0]), "+f"(c[1]), "+f"(c[2]), "+f"(c[3])
                 : "r"(a[0]), "r"(a[1]), "r"(a[2]), "r"(a[3]), "r"(b0), "r"(b1));
}

__device__ __forceinline__ void ldmatrix_x4(uint32_t r[4], uint32_t saddr) {
    asm volatile("ldmatrix.sync.aligned.m8n8.x4.shared.b16 {%0,%1,%2,%3}, [%4];"
                 : "=r"(r[0]), "=r"(r[1]), "=r"(r[2]), "=r"(r[3]) : "r"(saddr));
}

__device__ __forceinline__ uint32_t pack_h2(float x, float y) {
    __half2 h = __float22half2_rn(make_float2(x, y));
    return *(uint32_t*)&h;
}

// ===========================================================================
// fp16 HMMA GEMM:  C[m, n0..n0+127] = relu( sum_k A[m,k]*B[n,k] + bias[n] )
// A: [M, K] row-major (fp32 or fp16 per A_FP16), B: [256, K] row-major fp32.
// CTA tile 64(M) x 128(N), 8 warps of 32x32 (wm: 2 groups, wn: 4 groups).
// fp32 accumulators (32 regs); total ~110 regs -> 2 CTAs/SM under
// __launch_bounds__(256, 2) with no spills (occupancy was the R6 bottleneck).
// f32 -> f16 conversion once at staging. Double smem buffer, register
// prefetch of chunk c+1 overlapping compute of c, ONE __syncthreads per
// chunk (stores target the buffer whose readers drained before the previous
// end-of-chunk sync). ldmatrix rows at stride 40 halves (80B) ->
// conflict-free. Grid.x = tileM*2 + colTile (colTile fastest: 64-row A slab
// L2-hot on its 2nd N-tile).
// ===========================================================================
#define SROWH 40   // smem row stride in halves

template <int NCHUNK, bool A_FP16, bool OUT_FP16>
__global__ __launch_bounds__(256, 2) void gemm_f16_kernel(
    const void* __restrict__ Av, const float* __restrict__ B,
    const float* __restrict__ bias, void* __restrict__ Cv, int M)
{
    __shared__ __half sA[2][64 * SROWH];
    __shared__ __half sB[2][128 * SROWH];

    const int tid  = threadIdx.x;
    const int warp = tid >> 5;
    const int lane = tid & 31;
    const int g    = lane >> 2;
    const int tg   = lane & 3;
    const int m0   = (int)(blockIdx.x >> 1) * 64;
    const int n0   = (int)(blockIdx.x & 1) * 128;
    const int wm   = (warp >> 2) * 32;   // warp M offset (2 groups)
    const int wn   = (warp & 3) * 32;    // warp N offset (4 groups)
    const int K    = NCHUNK * 32;

    // A staging: 64 rows x 32 K; thread owns row tid>>2, 8 cols at (tid&3)*8
    const int arow = tid >> 2;
    const int acol = (tid & 3) * 8;
    // B staging: 128 rows x 32 K; thread owns row tid>>1, 16 cols at (tid&1)*16
    const int brow = tid >> 1;
    const int bcol = (tid & 1) * 16;
    const bool va  = (m0 + arow) < M;

    const float*  A32 = (const float*)Av;
    const __half* A16 = (const __half*)Av;

    float acc[2][4][4];
    #pragma unroll
    for (int i = 0; i < 2; i++)
        #pragma unroll
        for (int j = 0; j < 4; j++)
            #pragma unroll
            for (int r = 0; r < 4; r++) acc[i][j][r] = 0.f;

    // ---- stage chunk 0 into buffer 0 ----
    {
        #pragma unroll
        for (int i = 0; i < 2; i++) {
            uint2 ap;
            if (A_FP16) {
                ap = va ? *(const uint2*)(A16 + (size_t)(m0 + arow) * K + acol + i * 4)
                        : make_uint2(0u, 0u);
            } else {
                float4 v = va ? *(const float4*)(A32 + (size_t)(m0 + arow) * K + acol + i * 4)
                              : make_float4(0.f, 0.f, 0.f, 0.f);
                ap = make_uint2(pack_h2(v.x, v.y), pack_h2(v.z, v.w));
            }
            *(uint2*)&sA[0][arow * SROWH + acol + i * 4] = ap;
        }
        #pragma unroll
        for (int i = 0; i < 4; i++) {
            const float4 v = *(const float4*)(B + (size_t)(n0 + brow) * K + bcol + i * 4);
            *(uint2*)&sB[0][brow * SROWH + bcol + i * 4] =
                make_uint2(pack_h2(v.x, v.y), pack_h2(v.z, v.w));
        }
    }
    __syncthreads();

    const uint32_t uA0 = (uint32_t)__cvta_generic_to_shared(&sA[0][0]);
    const uint32_t uA1 = (uint32_t)__cvta_generic_to_shared(&sA[1][0]);
    const uint32_t uB0 = (uint32_t)__cvta_generic_to_shared(&sB[0][0]);
    const uint32_t uB1 = (uint32_t)__cvta_generic_to_shared(&sB[1][0]);

    const uint32_t offA = (uint32_t)(((lane & 15) * SROWH + (lane >> 4) * 8) * 2);
    const uint32_t offB = (uint32_t)((((lane >> 4) * 8 + (lane & 7)) * SROWH
                                      + ((lane >> 3) & 1) * 8) * 2);

    #pragma unroll 1
    for (int c = 0; c < NCHUNK; c++) {
        // ---- prefetch chunk c+1 into registers (overlaps mma) ----
        uint2  pa16[2];
        float4 pa32[2], pb[4];
        const bool havenext = (c + 1 < NCHUNK);
        if (havenext) {
            const int kk = (c + 1) * 32;
            #pragma unroll
            for (int i = 0; i < 2; i++) {
                if (A_FP16) {
                    pa16[i] = va ? *(const uint2*)(A16 + (size_t)(m0 + arow) * K + kk + acol + i * 4)
                                 : make_uint2(0u, 0u);
                } else {
                    pa32[i] = va ? *(const float4*)(A32 + (size_t)(m0 + arow) * K + kk + acol + i * 4)
                                 : make_float4(0.f, 0.f, 0.f, 0.f);
                }
            }
            #pragma unroll
            for (int i = 0; i < 4; i++)
                pb[i] = *(const float4*)(B + (size_t)(n0 + brow) * K + kk + bcol + i * 4);
        }

        // ---- compute chunk c ----
        const uint32_t ubA = (c & 1) ? uA1 : uA0;
        const uint32_t ubB = (c & 1) ? uB1 : uB0;
        #pragma unroll
        for (int ks = 0; ks < 2; ks++) {
            uint32_t af[2][4];
            #pragma unroll
            for (int mf = 0; mf < 2; mf++)
                ldmatrix_x4(af[mf], ubA + offA
                            + (uint32_t)(((wm + mf * 16) * SROWH + ks * 16) * 2));
            uint32_t bf[2][4];
            #pragma unroll
            for (int p = 0; p < 2; p++)
                ldmatrix_x4(bf[p], ubB + offB
                            + (uint32_t)(((wn + p * 16) * SROWH + ks * 16) * 2));
            #pragma unroll
            for (int mf = 0; mf < 2; mf++)
                #pragma unroll
                for (int nf = 0; nf < 4; nf++)
                    mma_f16_f32acc(acc[mf][nf], af[mf], bf[nf >> 1][(nf & 1) * 2],
                                   bf[nf >> 1][(nf & 1) * 2 + 1]);
        }

        // ---- store prefetched chunk c+1 into the other buffer ----
        // Safe without an extra barrier: that buffer's readers finished
        // before the sync that ended chunk c-1.
        if (havenext) {
            const uint32_t nb = (c + 1) & 1;
            __half* dA = nb ? &sA[1][0] : &sA[0][0];
            __half* dB = nb ? &sB[1][0] : &sB[0][0];
            #pragma unroll
            for (int i = 0; i < 2; i++) {
                uint2 ap;
                if (A_FP16) ap = pa16[i];
                else ap = make_uint2(pack_h2(pa32[i].x, pa32[i].y),
                                     pack_h2(pa32[i].z, pa32[i].w));
                *(uint2*)&dA[arow * SROWH + acol + i * 4] = ap;
            }
            #pragma unroll
            for (int i = 0; i < 4; i++)
                *(uint2*)&dB[brow * SROWH + bcol + i * 4] =
                    make_uint2(pack_h2(pb[i].x, pb[i].y), pack_h2(pb[i].z, pb[i].w));
        }
        __syncthreads();
    }

    // ---- epilogue: bias + relu, store (C row stride 256 elements) ----
    #pragma unroll
    for (int mf = 0; mf < 2; mf++) {
        #pragma unroll
        for (int half = 0; half < 2; half++) {
            const int m = m0 + wm + mf * 16 + g + half * 8;
            if (m < M) {
                #pragma unroll
                for (int nf = 0; nf < 4; nf++) {
                    const int cc = n0 + wn + nf * 8 + tg * 2;
                    const float v0 = fmaxf(acc[mf][nf][half * 2 + 0] + __ldg(&bias[cc]),     0.f);
                    const float v1 = fmaxf(acc[mf][nf][half * 2 + 1] + __ldg(&bias[cc + 1]), 0.f);
                    if (OUT_FP16) {
                        const uint32_t p = pack_h2(v0, v1);
                        *(uint32_t*)((__half*)Cv + (size_t)m * 256 + cc) = p;
                    } else {
                        *(float2*)((float*)Cv + (size_t)m * 256 + cc) = make_float2(v0, v1);
                    }
                }
            }
        }
    }
}

// ---------------------------------------------------------------------------
// Aggregation: h_agg[n] = sum_t w[n,t]*QH[nb[n,t]] / sum_t w[n,t]
// QH fp16 (L2-resident). One warp per node; also copies h[nodeset[n]]
// (fp32 -> fp16) into the first half of the fp16 concat row.
// ---------------------------------------------------------------------------
__global__ __launch_bounds__(256) void agg_kernel(
    const float* __restrict__ h, const int* __restrict__ nodeset,
    const int* __restrict__ nb_nodes, const float* __restrict__ nb_w)
{
    __shared__ int   s_idx[8][TN];
    __shared__ float s_w[8][TN];

    const int tid  = threadIdx.x;
    const int warp = tid >> 5;
    const int lane = tid & 31;
    const int n    = blockIdx.x * 8 + warp;   // 20000/8 = 2500 blocks exact

    for (int j = lane; j < TN; j += 32) {
        s_idx[warp][j] = nb_nodes[n * TN + j];
        s_w[warp][j]   = nb_w[n * TN + j];
    }
    __syncwarp();

    float wsum = 0.f;
    #pragma unroll
    for (int t = 0; t < TN; t++) wsum += s_w[warp][t];   // smem broadcast

    const int colb = lane * 8;
    float acc[8];
    #pragma unroll
    for (int i = 0; i < 8; i++) acc[i] = 0.f;

    #pragma unroll 10
    for (int t = 0; t < TN; t++) {
        const int   idx = s_idx[warp][t];
        const float w   = s_w[warp][t];
        union { uint4 u; __half2 h2[4]; } q;
        q.u = *(const uint4*)(g_qh + (size_t)idx * HIDF + colb);
        #pragma unroll
        for (int i = 0; i < 4; i++) {
            const float2 f = __half22float2(q.h2[i]);
            acc[2 * i]     += w * f.x;
            acc[2 * i + 1] += w * f.y;
        }
    }
    const float inv = 1.f / wsum;
    union { uint4 u; __half2 h2[4]; } o;
    #pragma unroll
    for (int i = 0; i < 4; i++)
        o.h2[i] = __float22half2_rn(make_float2(acc[2 * i] * inv, acc[2 * i + 1] * inv));
    *(uint4*)(g_cat + (size_t)n * CATF + INF + colb) = o.u;

    const int self = nodeset[n];
    const float4 s0 = *(const float4*)(h + (size_t)self * INF + colb);
    const float4 s1 = *(const float4*)(h + (size_t)self * INF + colb + 4);
    union { uint4 u; __half2 h2[4]; } sc;
    sc.h2[0] = __float22half2_rn(make_float2(s0.x, s0.y));
    sc.h2[1] = __float22half2_rn(make_float2(s0.z, s0.w));
    sc.h2[2] = __float22half2_rn(make_float2(s1.x, s1.y));
    sc.h2[3] = __float22half2_rn(make_float2(s1.z, s1.w));
    *(uint4*)(g_cat + (size_t)n * CATF + colb) = sc.u;
}

// ---------------------------------------------------------------------------
// In-place row L2 normalize of d_out [20000, 256]; one warp per row
// ---------------------------------------------------------------------------
__global__ __launch_bounds__(256) void norm_kernel(float* __restrict__ out)
{
    const int gwarp = (blockIdx.x * blockDim.x + threadIdx.x) >> 5;
    const int lane  = threadIdx.x & 31;
    if (gwarp >= NNODES) return;
    float* row = out + (size_t)gwarp * OUTF;

    float4 v0 = *(float4*)&row[lane * 4];
    float4 v1 = *(float4*)&row[128 + lane * 4];
    float ss = v0.x * v0.x + v0.y * v0.y + v0.z * v0.z + v0.w * v0.w
             + v1.x * v1.x + v1.y * v1.y + v1.z * v1.z + v1.w * v1.w;
    #pragma unroll
    for (int o = 16; o; o >>= 1) ss += __shfl_xor_sync(0xffffffffu, ss, o);
    const float inv = rsqrtf(ss);
    v0.x *= inv; v0.y *= inv; v0.z *= inv; v0.w *= inv;
    v1.x *= inv; v1.y *= inv; v1.z *= inv; v1.w *= inv;
    *(float4*)&row[lane * 4]       = v0;
    *(float4*)&row[128 + lane * 4] = v1;
}

// ---------------------------------------------------------------------------
extern "C" void kernel_launch(void* const* d_in, const int* in_sizes, int n_in,
                              void* d_out, int out_size)
{
    const float* h        = (const float*)d_in[0];
    const int*   nodeset  = (const int*)d_in[1];
    const int*   nb_nodes = (const int*)d_in[2];
    const float* nb_w     = (const float*)d_in[3];
    const float* Qw       = (const float*)d_in[4];
    const float* Qb       = (const float*)d_in[5];
    const float* Ww       = (const float*)d_in[6];
    const float* Wb       = (const float*)d_in[7];
    float*       out      = (float*)d_out;

    __half* qh  = nullptr;
    __half* cat = nullptr;
    cudaGetSymbolAddress((void**)&qh,  g_qh);
    cudaGetSymbolAddress((void**)&cat, g_cat);

    // 1) QH = relu(h @ Qw^T + Qb) -> fp16 [100000, 256], K=256 (8 chunks)
    {
        const int tilesM = (NODES_TOTAL + 63) / 64;   // 1563
        gemm_f16_kernel<8, false, true><<<tilesM * 2, 256>>>(h, Qw, Qb, qh, NODES_TOTAL);
    }
    // 2) aggregate + self gather -> g_cat fp16 [20000, 512]
    agg_kernel<<<NNODES / 8, 256>>>(h, nodeset, nb_nodes, nb_w);

    // 3) out = relu(g_cat @ Ww^T + Wb)  [20000, 256], K=512 (16 chunks)
    {
        const int tilesM = (NNODES + 63) / 64;        // 313
        gemm_f16_kernel<16, true, false><<<tilesM * 2, 256>>>(cat, Ww, Wb, out, NNODES);
    }
    // 4) in-place L2 normalize
    norm_kernel<<<(NNODES * 32 + 255) / 256, 256>>>(out);
}

// round 9
// speedup vs baseline: 1.1037x; 1.1037x over previous
#include <cuda_runtime.h>
#include <cuda_fp16.h>
#include <cstdint>

#define NODES_TOTAL 100000
#define NNODES      20000
#define TN          50
#define INF         256
#define HIDF        256
#define OUTF        256
#define CATF        512

// Scratch (static __device__ arrays: allocation-free per harness rules)
__device__ __align__(16) __half g_qh[(size_t)NODES_TOTAL * HIDF];  // 51.2 MB (L2-resident)
__device__ __align__(16) __half g_cat[(size_t)NNODES * CATF];      // 20.5 MB

// ---------------------------------------------------------------------------
// helpers
// ---------------------------------------------------------------------------
__device__ __forceinline__ void mma_f16_f32acc(float c[4], const uint32_t a[4],
                                               uint32_t b0, uint32_t b1) {
    asm volatile("mma.sync.aligned.m16n8k16.row.col.f32.f16.f16.f32 "
                 "{%0,%1,%2,%3}, {%4,%5,%6,%7}, {%8,%9}, {%0,%1,%2,%3};"
                 : "+f"(c[0]), "+f"(c[1]), "+f"(c[2]), "+f"(c[3])
                 : "r"(a[0]), "r"(a[1]), "r"(a[2]), "r"(a[3]), "r"(b0), "r"(b1));
}

__device__ __forceinline__ void ldmatrix_x4(uint32_t r[4], uint32_t saddr) {
    asm volatile("ldmatrix.sync.aligned.m8n8.x4.shared.b16 {%0,%1,%2,%3}, [%4];"
                 : "=r"(r[0]), "=r"(r[1]), "=r"(r[2]), "=r"(r[3]) : "r"(saddr));
}

__device__ __forceinline__ uint32_t pack_h2(float x, float y) {
    __half2 h = __float22half2_rn(make_float2(x, y));
    return *(uint32_t*)&h;
}

// ===========================================================================
// fp16 HMMA GEMM:  C[m, n0..n0+127] = relu( sum_k A[m,k]*B[n,k] + bias[n] )
// A: [M, K] row-major (fp32 or fp16 per A_FP16), B: [256, K] row-major fp32.
// CTA tile 128x128, 8 warps (64x32 each), K chunked by 32.
// R9 experiment: NO prefetch registers. Chunk c+1 is staged (LDG->cvt->STS)
// AFTER the mma block of chunk c; __launch_bounds__(256,2) caps regs at 128
// so 2 CTAs are resident per SM (vs 1 in R6) — inter-CTA overlap hides the
// staging latency; ptxas may hoist the dependence-free LDGs into the mma
// block up to the register budget (adaptive prefetch).
// Double smem buffer, ONE __syncthreads per chunk (stores target the buffer
// whose readers drained before the previous end-of-chunk sync).
// ldmatrix rows at stride 40 halves (80B) -> conflict-free.
// Grid.x = tileM*2 + colTile (colTile fastest: A slab L2-hot on 2nd N-tile).
// ===========================================================================
#define SROWH 40   // smem row stride in halves

template <int NCHUNK, bool A_FP16, bool OUT_FP16>
__global__ __launch_bounds__(256, 2) void gemm_f16_kernel(
    const void* __restrict__ Av, const float* __restrict__ B,
    const float* __restrict__ bias, void* __restrict__ Cv, int M)
{
    __shared__ __half sA[2][128 * SROWH];
    __shared__ __half sB[2][128 * SROWH];

    const int tid  = threadIdx.x;
    const int warp = tid >> 5;
    const int lane = tid & 31;
    const int g    = lane >> 2;
    const int tg   = lane & 3;
    const int m0   = (int)(blockIdx.x >> 1) * 128;
    const int n0   = (int)(blockIdx.x & 1) * 128;
    const int wm   = (warp >> 2) * 64;   // warp M offset
    const int wn   = (warp & 3) * 32;    // warp N offset
    const int K    = NCHUNK * 32;

    // staging: each thread owns row tid>>1, 16-half slot (tid&1)*16
    const int srow = tid >> 1;
    const int part = (tid & 1) * 16;
    const bool va  = (m0 + srow) < M;

    const float*  A32 = (const float*)Av;
    const __half* A16 = (const __half*)Av;

    float acc[4][4][4];
    #pragma unroll
    for (int i = 0; i < 4; i++)
        #pragma unroll
        for (int j = 0; j < 4; j++)
            #pragma unroll
            for (int r = 0; r < 4; r++) acc[i][j][r] = 0.f;

    // ---- stage chunk 0 into buffer 0 ----
    #pragma unroll
    for (int i = 0; i < 4; i++) {
        const int kc = part + i * 4;
        uint2 apk;
        if (A_FP16) {
            apk = va ? *(const uint2*)(A16 + (size_t)(m0 + srow) * K + kc)
                     : make_uint2(0u, 0u);
        } else {
            float4 v = va ? *(const float4*)(A32 + (size_t)(m0 + srow) * K + kc)
                          : make_float4(0.f, 0.f, 0.f, 0.f);
            apk = make_uint2(pack_h2(v.x, v.y), pack_h2(v.z, v.w));
        }
        *(uint2*)&sA[0][srow * SROWH + kc] = apk;
        float4 vb = *(const float4*)(B + (size_t)(n0 + srow) * K + kc);
        *(uint2*)&sB[0][srow * SROWH + kc] =
            make_uint2(pack_h2(vb.x, vb.y), pack_h2(vb.z, vb.w));
    }
    __syncthreads();

    const uint32_t uA0 = (uint32_t)__cvta_generic_to_shared(&sA[0][0]);
    const uint32_t uA1 = (uint32_t)__cvta_generic_to_shared(&sA[1][0]);
    const uint32_t uB0 = (uint32_t)__cvta_generic_to_shared(&sB[0][0]);
    const uint32_t uB1 = (uint32_t)__cvta_generic_to_shared(&sB[1][0]);

    const uint32_t offA = (uint32_t)(((lane & 15) * SROWH + (lane >> 4) * 8) * 2);
    const uint32_t offB = (uint32_t)((((lane >> 4) * 8 + (lane & 7)) * SROWH
                                      + ((lane >> 3) & 1) * 8) * 2);

    #pragma unroll 1
    for (int c = 0; c < NCHUNK; c++) {
        // ---- compute chunk c ----
        const uint32_t ubA = (c & 1) ? uA1 : uA0;
        const uint32_t ubB = (c & 1) ? uB1 : uB0;
        #pragma unroll
        for (int ks = 0; ks < 2; ks++) {
            uint32_t af[4][4];
            #pragma unroll
            for (int mf = 0; mf < 4; mf++)
                ldmatrix_x4(af[mf], ubA + offA
                            + (uint32_t)(((wm + mf * 16) * SROWH + ks * 16) * 2));
            uint32_t bf[2][4];
            #pragma unroll
            for (int p = 0; p < 2; p++)
                ldmatrix_x4(bf[p], ubB + offB
                            + (uint32_t)(((wn + p * 16) * SROWH + ks * 16) * 2));
            #pragma unroll
            for (int mf = 0; mf < 4; mf++)
                #pragma unroll
                for (int nf = 0; nf < 4; nf++)
                    mma_f16_f32acc(acc[mf][nf], af[mf], bf[nf >> 1][(nf & 1) * 2],
                                   bf[nf >> 1][(nf & 1) * 2 + 1]);
        }

        // ---- stage chunk c+1 into the other buffer (no prefetch regs) ----
        // Safe: that buffer's readers finished before the sync ending the
        // previous chunk. 2 resident CTAs/SM hide the LDG->STS latency.
        if (c + 1 < NCHUNK) {
            const int kk = (c + 1) * 32 + part;
            __half* dA = ((c + 1) & 1) ? &sA[1][0] : &sA[0][0];
            __half* dB = ((c + 1) & 1) ? &sB[1][0] : &sB[0][0];
            #pragma unroll
            for (int i = 0; i < 4; i++) {
                uint2 apk;
                if (A_FP16) {
                    apk = va ? *(const uint2*)(A16 + (size_t)(m0 + srow) * K + kk + i * 4)
                             : make_uint2(0u, 0u);
                } else {
                    float4 v = va ? *(const float4*)(A32 + (size_t)(m0 + srow) * K + kk + i * 4)
                                  : make_float4(0.f, 0.f, 0.f, 0.f);
                    apk = make_uint2(pack_h2(v.x, v.y), pack_h2(v.z, v.w));
                }
                *(uint2*)&dA[srow * SROWH + part + i * 4] = apk;
                float4 vb = *(const float4*)(B + (size_t)(n0 + srow) * K + kk + i * 4);
                *(uint2*)&dB[srow * SROWH + part + i * 4] =
                    make_uint2(pack_h2(vb.x, vb.y), pack_h2(vb.z, vb.w));
            }
        }
        __syncthreads();
    }

    // ---- epilogue: bias + relu, store (C row stride 256 elements) ----
    #pragma unroll
    for (int mf = 0; mf < 4; mf++) {
        #pragma unroll
        for (int half = 0; half < 2; half++) {
            const int m = m0 + wm + mf * 16 + g + half * 8;
            if (m < M) {
                #pragma unroll
                for (int nf = 0; nf < 4; nf++) {
                    const int cc = n0 + wn + nf * 8 + tg * 2;
                    const float v0 = fmaxf(acc[mf][nf][half * 2 + 0] + __ldg(&bias[cc]),     0.f);
                    const float v1 = fmaxf(acc[mf][nf][half * 2 + 1] + __ldg(&bias[cc + 1]), 0.f);
                    if (OUT_FP16) {
                        const uint32_t p = pack_h2(v0, v1);
                        *(uint32_t*)((__half*)Cv + (size_t)m * 256 + cc) = p;
                    } else {
                        *(float2*)((float*)Cv + (size_t)m * 256 + cc) = make_float2(v0, v1);
                    }
                }
            }
        }
    }
}

// ---------------------------------------------------------------------------
// Aggregation: h_agg[n] = sum_t w[n,t]*QH[nb[n,t]] / sum_t w[n,t]
// QH fp16 (L2-resident, ~45us = near the L2 gather floor of 512MB @ ~11TB/s).
// One warp per node; also copies h[nodeset[n]] (fp32 -> fp16) into the first
// half of the fp16 concat row.
// ---------------------------------------------------------------------------
__global__ __launch_bounds__(256) void agg_kernel(
    const float* __restrict__ h, const int* __restrict__ nodeset,
    const int* __restrict__ nb_nodes, const float* __restrict__ nb_w)
{
    __shared__ int   s_idx[8][TN];
    __shared__ float s_w[8][TN];

    const int tid  = threadIdx.x;
    const int warp = tid >> 5;
    const int lane = tid & 31;
    const int n    = blockIdx.x * 8 + warp;   // 20000/8 = 2500 blocks exact

    for (int j = lane; j < TN; j += 32) {
        s_idx[warp][j] = nb_nodes[n * TN + j];
        s_w[warp][j]   = nb_w[n * TN + j];
    }
    __syncwarp();

    float wsum = 0.f;
    #pragma unroll
    for (int t = 0; t < TN; t++) wsum += s_w[warp][t];   // smem broadcast

    const int colb = lane * 8;
    float acc[8];
    #pragma unroll
    for (int i = 0; i < 8; i++) acc[i] = 0.f;

    #pragma unroll 10
    for (int t = 0; t < TN; t++) {
        const int   idx = s_idx[warp][t];
        const float w   = s_w[warp][t];
        union { uint4 u; __half2 h2[4]; } q;
        q.u = *(const uint4*)(g_qh + (size_t)idx * HIDF + colb);
        #pragma unroll
        for (int i = 0; i < 4; i++) {
            const float2 f = __half22float2(q.h2[i]);
            acc[2 * i]     += w * f.x;
            acc[2 * i + 1] += w * f.y;
        }
    }
    const float inv = 1.f / wsum;
    union { uint4 u; __half2 h2[4]; } o;
    #pragma unroll
    for (int i = 0; i < 4; i++)
        o.h2[i] = __float22half2_rn(make_float2(acc[2 * i] * inv, acc[2 * i + 1] * inv));
    *(uint4*)(g_cat + (size_t)n * CATF + INF + colb) = o.u;

    const int self = nodeset[n];
    const float4 s0 = *(const float4*)(h + (size_t)self * INF + colb);
    const float4 s1 = *(const float4*)(h + (size_t)self * INF + colb + 4);
    union { uint4 u; __half2 h2[4]; } sc;
    sc.h2[0] = __float22half2_rn(make_float2(s0.x, s0.y));
    sc.h2[1] = __float22half2_rn(make_float2(s0.z, s0.w));
    sc.h2[2] = __float22half2_rn(make_float2(s1.x, s1.y));
    sc.h2[3] = __float22half2_rn(make_float2(s1.z, s1.w));
    *(uint4*)(g_cat + (size_t)n * CATF + colb) = sc.u;
}

// ---------------------------------------------------------------------------
// In-place row L2 normalize of d_out [20000, 256]; one warp per row
// ---------------------------------------------------------------------------
__global__ __launch_bounds__(256) void norm_kernel(float* __restrict__ out)
{
    const int gwarp = (blockIdx.x * blockDim.x + threadIdx.x) >> 5;
    const int lane  = threadIdx.x & 31;
    if (gwarp >= NNODES) return;
    float* row = out + (size_t)gwarp * OUTF;

    float4 v0 = *(float4*)&row[lane * 4];
    float4 v1 = *(float4*)&row[128 + lane * 4];
    float ss = v0.x * v0.x + v0.y * v0.y + v0.z * v0.z + v0.w * v0.w
             + v1.x * v1.x + v1.y * v1.y + v1.z * v1.z + v1.w * v1.w;
    #pragma unroll
    for (int o = 16; o; o >>= 1) ss += __shfl_xor_sync(0xffffffffu, ss, o);
    const float inv = rsqrtf(ss);
    v0.x *= inv; v0.y *= inv; v0.z *= inv; v0.w *= inv;
    v1.x *= inv; v1.y *= inv; v1.z *= inv; v1.w *= inv;
    *(float4*)&row[lane * 4]       = v0;
    *(float4*)&row[128 + lane * 4] = v1;
}

// ---------------------------------------------------------------------------
extern "C" void kernel_launch(void* const* d_in, const int* in_sizes, int n_in,
                              void* d_out, int out_size)
{
    const float* h        = (const float*)d_in[0];
    const int*   nodeset  = (const int*)d_in[1];
    const int*   nb_nodes = (const int*)d_in[2];
    const float* nb_w     = (const float*)d_in[3];
    const float* Qw       = (const float*)d_in[4];
    const float* Qb       = (const float*)d_in[5];
    const float* Ww       = (const float*)d_in[6];
    const float* Wb       = (const float*)d_in[7];
    float*       out      = (float*)d_out;

    __half* qh  = nullptr;
    __half* cat = nullptr;
    cudaGetSymbolAddress((void**)&qh,  g_qh);
    cudaGetSymbolAddress((void**)&cat, g_cat);

    // 1) QH = relu(h @ Qw^T + Qb) -> fp16 [100000, 256], K=256 (8 chunks)
    {
        const int tilesM = (NODES_TOTAL + 127) / 128;   // 782
        gemm_f16_kernel<8, false, true><<<tilesM * 2, 256>>>(h, Qw, Qb, qh, NODES_TOTAL);
    }
    // 2) aggregate + self gather -> g_cat fp16 [20000, 512]
    agg_kernel<<<NNODES / 8, 256>>>(h, nodeset, nb_nodes, nb_w);

    // 3) out = relu(g_cat @ Ww^T + Wb)  [20000, 256], K=512 (16 chunks)
    {
        const int tilesM = (NNODES + 127) / 128;        // 157
        gemm_f16_kernel<16, true, false><<<tilesM * 2, 256>>>(cat, Ww, Wb, out, NNODES);
    }
    // 4) in-place L2 normalize
    norm_kernel<<<(NNODES * 32 + 255) / 256, 256>>>(out);
}